// round 3
// baseline (speedup 1.0000x reference)
#include <cuda_runtime.h>
#include <math.h>

// ---------------- static scratch ----------------
__device__ __align__(256) float g_EMB[512*64*256];
__device__ __align__(256) float g_XA [512*64*512];
__device__ __align__(256) float g_XB [512*64*512];
__device__ __align__(256) float g_GT [512*64*2048];
__device__ __align__(256) float g_T0 [512*64*256];
__device__ __align__(256) float g_T1 [512*64*256];
__device__ __align__(256) float g_P0 [512*64*256];
__device__ __align__(256) float g_P1 [512*64*256];
__device__ __align__(256) float g_H  [2*2*256*64];   // [pp][dir][k][b]
__device__ __align__(256) float g_FU [64*774];
__device__ __align__(256) float g_S1 [64*512];
__device__ __align__(256) float g_S2 [64*256];
__device__ unsigned g_bar;

// ---------------- helpers ----------------
__device__ __forceinline__ unsigned long long pk2(float lo, float hi){
    unsigned long long u; asm("mov.b64 %0,{%1,%2};":"=l"(u):"f"(lo),"f"(hi)); return u;
}
__device__ __forceinline__ void fma2(unsigned long long&d,unsigned long long a,unsigned long long b){
    asm("fma.rn.f32x2 %0,%1,%2,%0;":"+l"(d):"l"(a),"l"(b));
}
__device__ __forceinline__ void upk2(unsigned long long u,float&lo,float&hi){
    asm("mov.b64 {%0,%1},%2;":"=f"(lo),"=f"(hi):"l"(u));
}
__device__ __forceinline__ float sigm(float x){ return 1.f/(1.f+__expf(-x)); }

// ---------------- embedding gather ----------------
__global__ void k_embed(const int* __restrict__ seq, const float* __restrict__ tab){
    int m = blockIdx.x; int s = m>>6, b = m&63;
    long tok = seq[b*512+s];
    const float4* src = (const float4*)(tab + tok*256);
    ((float4*)(g_EMB + (long)m*256))[threadIdx.x] = src[threadIdx.x];
}

__global__ void k_rst(){ g_bar = 0u; }

// ---------------- GEMM: C[M,N] = A[M,K] @ W[N,K]^T + bias ----------------
// 64x64 tile, 256 threads, 4x4 micro-tile, f32x2 over N. K % 16 == 0.
__global__ void __launch_bounds__(256) k_gemm(const float* __restrict__ A,
        const float* __restrict__ W, const float* __restrict__ bias,
        float* __restrict__ C, int K, int N){
    __shared__ float As[16][68];
    __shared__ float Bs[16][68];
    int tid = threadIdx.x;
    int m0 = blockIdx.y*64, n0 = blockIdx.x*64;
    int lr = tid>>2, lk = (tid&3)*4;
    const float* Ag = A + (long)(m0+lr)*K + lk;
    const float* Wg = W + (long)(n0+lr)*K + lk;
    int tx = tid&15, ty = tid>>4;
    unsigned long long acc[4][2];
#pragma unroll
    for(int i=0;i<4;i++){ acc[i][0]=0ULL; acc[i][1]=0ULL; }
    for(int kt=0; kt<K; kt+=16){
        float4 a4 = *(const float4*)(Ag+kt);
        float4 b4 = *(const float4*)(Wg+kt);
        As[lk+0][lr]=a4.x; As[lk+1][lr]=a4.y; As[lk+2][lr]=a4.z; As[lk+3][lr]=a4.w;
        Bs[lk+0][lr]=b4.x; Bs[lk+1][lr]=b4.y; Bs[lk+2][lr]=b4.z; Bs[lk+3][lr]=b4.w;
        __syncthreads();
#pragma unroll
        for(int k=0;k<16;k++){
            float4 av = *(const float4*)&As[k][ty*4];
            ulonglong2 bv = *(const ulonglong2*)&Bs[k][tx*4];
            unsigned long long a0=pk2(av.x,av.x), a1=pk2(av.y,av.y);
            unsigned long long a2=pk2(av.z,av.z), a3=pk2(av.w,av.w);
            fma2(acc[0][0],a0,bv.x); fma2(acc[0][1],a0,bv.y);
            fma2(acc[1][0],a1,bv.x); fma2(acc[1][1],a1,bv.y);
            fma2(acc[2][0],a2,bv.x); fma2(acc[2][1],a2,bv.y);
            fma2(acc[3][0],a3,bv.x); fma2(acc[3][1],a3,bv.y);
        }
        __syncthreads();
    }
    const float* bp = bias + n0 + tx*4;
    float b0v=bp[0], b1v=bp[1], b2v=bp[2], b3v=bp[3];
#pragma unroll
    for(int i=0;i<4;i++){
        float x0,x1,x2,x3; upk2(acc[i][0],x0,x1); upk2(acc[i][1],x2,x3);
        long m = m0 + ty*4 + i;
        *(float4*)(C + m*N + n0 + tx*4) = make_float4(x0+b0v,x1+b1v,x2+b2v,x3+b3v);
    }
}

// ---------------- persistent bidirectional LSTM layer ----------------
__device__ __forceinline__ void gbar(unsigned target){
    __syncthreads();
    if(threadIdx.x==0){
        __threadfence();
        atomicAdd(&g_bar,1u);
        while(*(volatile unsigned*)&g_bar < target) __nanosleep(64);
        __threadfence();
    }
    __syncthreads();
}

#define WST 257            // padded Whh smem row stride
#define LSMEM ((64*WST + 256*16 + 64*16 + 256)*4)

__global__ void __launch_bounds__(256) k_lstm(const float* __restrict__ gates,
        const float* __restrict__ WhhA, const float* __restrict__ WhhB,
        float* __restrict__ out){
    extern __shared__ float sm[];
    float* Wsh = sm;                       // [64][WST]
    float* hsh = sm + 64*WST;              // [256][16]
    float* gsh = hsh + 256*16;             // [64][16]
    float* csh = gsh + 64*16;              // [16][16]
    int tid = threadIdx.x, bid = blockIdx.x;
    int dir = bid>>6, hb = (bid>>2)&15, bg = bid&3;
    int hu0 = hb*16, b0 = bg*16;
    const float* Whh = dir ? WhhB : WhhA;
    // load Whh slice: local row g*16+u <- global row g*256+hu0+u
    for(int i=tid;i<4096;i+=256){
        int lrw = i>>6, c4 = (i&63)*4;
        int gg = lrw>>4, u = lrw&15;
        float4 v = *(const float4*)(Whh + (long)(gg*256+hu0+u)*256 + c4);
        Wsh[lrw*WST+c4+0]=v.x; Wsh[lrw*WST+c4+1]=v.y;
        Wsh[lrw*WST+c4+2]=v.z; Wsh[lrw*WST+c4+3]=v.w;
    }
    csh[tid>>4==0 ? tid : tid] = 0.f;      // 256 threads cover 16x16
    csh[tid] = 0.f;
    { int k = hu0 + (tid>>4), b = b0 + (tid&15);
      g_H[((long)(0*2+dir)*256 + k)*64 + b] = 0.f; }
    unsigned tc = 128;
    gbar(tc);
    int r = tid&63, q = tid>>6;
    int u = tid>>4, bb = tid&15;
    const float* wr = Wsh + r*WST;
    const float* hq = hsh + q*4;
    for(int si=0; si<512; si++){
        int s = dir ? 511-si : si;
        int pp = si&1;
        for(int i=tid;i<1024;i+=256){
            int k=i>>2, c4=i&3;
            float4 v = __ldcg(((const float4*)(g_H + (((long)pp*2+dir)*256+k)*64 + b0)) + c4);
            *(float4*)(hsh + k*16 + c4*4) = v;
        }
        __syncthreads();
        unsigned long long a0=0ULL, a1=0ULL;
#pragma unroll 8
        for(int k=0;k<256;k++){
            float w = wr[k];
            unsigned long long w2 = pk2(w,w);
            ulonglong2 hv = *(const ulonglong2*)(hq + k*16);
            fma2(a0,w2,hv.x); fma2(a1,w2,hv.y);
        }
        float x0,x1,x2,x3; upk2(a0,x0,x1); upk2(a1,x2,x3);
        *(float4*)(gsh + r*16 + q*4) = make_float4(x0,x1,x2,x3);
        __syncthreads();
        long gb = ((long)s*64 + b0+bb)*2048 + dir*1024 + hu0 + u;
        float gi = gsh[(  u)*16+bb] + __ldg(gates+gb);
        float gf = gsh[(16+u)*16+bb] + __ldg(gates+gb+256);
        float gg = gsh[(32+u)*16+bb] + __ldg(gates+gb+512);
        float go = gsh[(48+u)*16+bb] + __ldg(gates+gb+768);
        float c = csh[u*16+bb];
        c = sigm(gf)*c + sigm(gi)*tanhf(gg);
        float h = sigm(go)*tanhf(c);
        csh[u*16+bb] = c;
        g_H[(((long)(1-pp)*2+dir)*256 + hu0+u)*64 + b0+bb] = h;
        out[((long)s*64 + b0+bb)*512 + dir*256 + hu0+u] = h;
        tc += 128;
        gbar(tc);
    }
}

// ---------------- GCN banded adjacency ----------------
__global__ void k_band(const float* __restrict__ x, const float* __restrict__ mask,
                       float* __restrict__ o){
    int m = blockIdx.x; int s=m>>6, b=m&63;
    float mm = mask[b*512+s];
    float mn = (s<511)? mask[b*512+s+1] : 0.f;
    float mp = (s>0)?   mask[b*512+s-1] : 0.f;
    float rs = mm*(mp+mn)+1e-8f;
    float cn = mm*mn/rs, cp = mm*mp/rs;
    int t = threadIdx.x;
    float4 vn = (s<511)? ((const float4*)(x+((long)m+64)*256))[t] : make_float4(0,0,0,0);
    float4 vp = (s>0)?   ((const float4*)(x+((long)m-64)*256))[t] : make_float4(0,0,0,0);
    float4 r; r.x=cn*vn.x+cp*vp.x; r.y=cn*vn.y+cp*vp.y;
    r.z=cn*vn.z+cp*vp.z; r.w=cn*vn.w+cp*vp.w;
    ((float4*)(o+(long)m*256))[t]=r;
}

// ---------------- residual + LayerNorm + ReLU ----------------
__global__ void k_ln(const float* __restrict__ go, const float* __restrict__ xin,
                     const float* __restrict__ gamma, const float* __restrict__ beta,
                     float* __restrict__ o){
    __shared__ float rs1[8], rs2[8];
    long m = blockIdx.x; int t = threadIdx.x;
    float v = go[m*256+t] + xin[m*256+t];
    float s1=v, s2=v*v;
#pragma unroll
    for(int w=16;w;w>>=1){ s1+=__shfl_xor_sync(~0u,s1,w); s2+=__shfl_xor_sync(~0u,s2,w); }
    if((t&31)==0){ rs1[t>>5]=s1; rs2[t>>5]=s2; }
    __syncthreads();
    float S1=0,S2=0;
#pragma unroll
    for(int i=0;i<8;i++){ S1+=rs1[i]; S2+=rs2[i]; }
    float mu=S1*(1.f/256.f), var=S2*(1.f/256.f)-mu*mu;
    float inv=rsqrtf(var+1e-5f);
    float y=(v-mu)*inv*gamma[t]+beta[t];
    o[m*256+t]=fmaxf(y,0.f);
}

// ---------------- masked mean pooling + fuse ----------------
__global__ void k_pool(const float* __restrict__ lstm, const float* __restrict__ gcn,
                       const float* __restrict__ mask, const float* __restrict__ aux){
    int b = blockIdx.x, t = threadIdx.x;
    float dn=0.f;
    for(int s=0;s<512;s++) dn += mask[b*512+s];
    dn = fmaxf(dn,1e-8f);
    float acc=0.f;
    for(int s=0;s<512;s++) acc += lstm[((long)s*64+b)*512+t]*mask[b*512+s];
    g_FU[b*774+t]=acc/dn;
    if(t<256){
        float a2=0.f;
        for(int s=0;s<512;s++) a2 += gcn[((long)s*64+b)*256+t]*mask[b*512+s];
        g_FU[b*774+512+t]=a2/dn;
    }
    if(t<6) g_FU[b*774+768+t]=aux[b*6+t];
}

// ---------------- small FC ----------------
__global__ void k_fc(const float* __restrict__ in, const float* __restrict__ W,
                     const float* __restrict__ bias, float* __restrict__ o,
                     int K, int N, int relu){
    int idx = blockIdx.x*blockDim.x + threadIdx.x;
    if(idx >= 64*N) return;
    int b = idx/N, n = idx%N;
    const float* ip = in + (long)b*K;
    const float* wp = W + (long)n*K;
    float a=0.f;
    for(int k=0;k<K;k++) a += ip[k]*wp[k];
    a += bias[n];
    o[idx] = relu ? fmaxf(a,0.f) : a;
}

// ---------------- launch ----------------
extern "C" void kernel_launch(void* const* d_in, const int* in_sizes, int n_in,
                              void* d_out, int out_size){
    const int*   seq  = (const int*)  d_in[0];
    const float* mask = (const float*)d_in[1];
    const float* aux  = (const float*)d_in[2];
    const float* emb  = (const float*)d_in[3];
    const float* Wih0 = (const float*)d_in[4];
    const float* Whh0 = (const float*)d_in[5];
    const float* b0   = (const float*)d_in[6];
    const float* WihL = (const float*)d_in[7];
    const float* WhhL = (const float*)d_in[8];
    const float* bLp  = (const float*)d_in[9];
    const float* gW   = (const float*)d_in[10];
    const float* gb   = (const float*)d_in[11];
    const float* gga  = (const float*)d_in[12];
    const float* gbe  = (const float*)d_in[13];
    const float* f1W  = (const float*)d_in[14];
    const float* f1b  = (const float*)d_in[15];
    const float* f2W  = (const float*)d_in[16];
    const float* f2b  = (const float*)d_in[17];
    const float* h0W  = (const float*)d_in[18];
    const float* h0b  = (const float*)d_in[19];
    const float* h1W  = (const float*)d_in[20];
    const float* h1b  = (const float*)d_in[21];
    float* out = (float*)d_out;

    float *pEMB,*pXA,*pXB,*pGT,*pT0,*pT1,*pP0,*pP1,*pFU,*pS1,*pS2;
    cudaGetSymbolAddress((void**)&pEMB,g_EMB);
    cudaGetSymbolAddress((void**)&pXA, g_XA);
    cudaGetSymbolAddress((void**)&pXB, g_XB);
    cudaGetSymbolAddress((void**)&pGT, g_GT);
    cudaGetSymbolAddress((void**)&pT0, g_T0);
    cudaGetSymbolAddress((void**)&pT1, g_T1);
    cudaGetSymbolAddress((void**)&pP0, g_P0);
    cudaGetSymbolAddress((void**)&pP1, g_P1);
    cudaGetSymbolAddress((void**)&pFU, g_FU);
    cudaGetSymbolAddress((void**)&pS1, g_S1);
    cudaGetSymbolAddress((void**)&pS2, g_S2);
    cudaFuncSetAttribute(k_lstm, cudaFuncAttributeMaxDynamicSharedMemorySize, LSMEM);

    k_embed<<<32768,64>>>(seq, emb);

    const float* inp = pEMB; int K = 256;
    float* lo = pXA;
    for(int l=0;l<5;l++){
        const float* wih = l ? WihL + (long)(l-1)*2*1024*512 : Wih0;
        const float* whh = l ? WhhL + (long)(l-1)*2*1024*256 : Whh0;
        const float* bb  = l ? bLp  + (long)(l-1)*2*1024      : b0;
        dim3 gg(2048/64, 32768/64);
        k_gemm<<<gg,256>>>(inp, wih, bb, pGT, K, 2048);
        k_rst<<<1,1>>>();
        lo = (l&1) ? pXB : pXA;
        k_lstm<<<128,256,LSMEM>>>(pGT, whh, whh + 1024*256, lo);
        inp = lo; K = 512;
    }
    const float* lstmOut = lo;

    const float* gin = pEMB;
    float* gout = pP0;
    for(int i=0;i<3;i++){
        k_band<<<32768,64>>>(gin, mask, pT0);
        dim3 gg(256/64, 32768/64);
        k_gemm<<<gg,256>>>(pT0, gW + (long)i*256*256, gb + i*256, pT1, 256, 256);
        gout = (i&1) ? pP1 : pP0;
        k_ln<<<32768,256>>>(pT1, gin, gga + i*256, gbe + i*256, gout);
        gin = gout;
    }

    k_pool<<<64,512>>>(lstmOut, gout, mask, aux);
    k_fc<<<(64*512+255)/256,256>>>(pFU, f1W, f1b, pS1, 774, 512, 1);
    k_fc<<<(64*256+255)/256,256>>>(pS1, f2W, f2b, pS2, 512, 256, 1);
    k_fc<<<(64*10+255)/256,256>>>(pS2, h0W, h0b, out,      256, 10, 0);
    k_fc<<<(64*5 +255)/256,256>>>(pS2, h1W, h1b, out+640, 256,  5, 0);
}